// round 15
// baseline (speedup 1.0000x reference)
#include <cuda_runtime.h>
#include <cuda_fp16.h>
#include <cstdint>

#define Bdim   8
#define Ndim   32
#define Cdim   768
#define Tdim   256
#define KTOP   5
#define BNprod (Bdim * Ndim)

// Output layout (float32, concatenated in return-tuple order)
#define OFF_ID      0
#define OFF_SCORE   40
#define OFF_SPTS    80
#define OFF_TAR     10320
#define OFF_SRC     30800
#define OFF_CNT     51280

// ---------------- global scratch ----------------
__device__ unsigned long long g_t2sP[4][BNprod * Tdim];  // row max parts (s-quarters)
__device__ unsigned long long g_s2t[BNprod * Tdim];      // col max (complete per CTA)
__device__ float              g_mask_all[BNprod * Tdim];
__device__ float              g_simavg[BNprod];

__device__ __half g_AH[(size_t)Bdim * Cdim * Tdim];      // tar hi (3.1MB)
__device__ __half g_AL[(size_t)Bdim * Cdim * Tdim];      // tar lo
__device__ float  g_fT[Bdim * Tdim];                     // inv_norm * tar_mask
__device__ float  g_psq[8][Bdim * Tdim];                 // partial sumsq (C-chunks)

static __device__ __forceinline__ unsigned long long packsi(float score, int idx) {
    return ((unsigned long long)__float_as_uint(score) << 32) |
           (unsigned long long)(unsigned)(~idx);
}
static __device__ __forceinline__ unsigned long long umaxll(unsigned long long a,
                                                            unsigned long long b) {
    return a > b ? a : b;
}
static __device__ __forceinline__ uint32_t smem_u32(const void* p) {
    uint32_t a;
    asm("{ .reg .u64 t; cvta.to.shared.u64 t, %1; cvt.u32.u64 %0, t; }" : "=r"(a) : "l"(p));
    return a;
}
static __device__ __forceinline__ void ldm4t(uint32_t* r, uint32_t addr) {
    asm volatile("ldmatrix.sync.aligned.m8n8.x4.trans.shared.b16 {%0,%1,%2,%3}, [%4];"
                 : "=r"(r[0]), "=r"(r[1]), "=r"(r[2]), "=r"(r[3]) : "r"(addr));
}
static __device__ __forceinline__ void mma16816(float* d, const uint32_t* a,
                                                const uint32_t* b) {
    asm volatile(
        "mma.sync.aligned.m16n8k16.row.col.f32.f16.f16.f32 "
        "{%0,%1,%2,%3}, {%4,%5,%6,%7}, {%8,%9}, {%0,%1,%2,%3};"
        : "+f"(d[0]), "+f"(d[1]), "+f"(d[2]), "+f"(d[3])
        : "r"(a[0]), "r"(a[1]), "r"(a[2]), "r"(a[3]), "r"(b[0]), "r"(b[1]));
}
static __device__ __forceinline__ void cpasync16(uint32_t dst, const void* src) {
    asm volatile("cp.async.cg.shared.global [%0], [%1], 16;" :: "r"(dst), "l"(src)
                 : "memory");
}
#define CP_COMMIT()  asm volatile("cp.async.commit_group;" ::: "memory")
#define CP_WAIT(n)   asm volatile("cp.async.wait_group %0;" :: "n"(n) : "memory")

static __device__ __forceinline__ void sts64(uint32_t addr, uint32_t r0, uint32_t r1) {
    asm volatile("st.shared.v2.b32 [%0], {%1, %2};" :: "r"(addr), "r"(r0), "r"(r1)
                 : "memory");
}
static __device__ __forceinline__ void cvt4(float4 v, float* sq,
                                            uint32_t& hi0, uint32_t& hi1,
                                            uint32_t& lo0, uint32_t& lo1) {
    sq[0] = fmaf(v.x, v.x, sq[0]);
    sq[1] = fmaf(v.y, v.y, sq[1]);
    sq[2] = fmaf(v.z, v.z, sq[2]);
    sq[3] = fmaf(v.w, v.w, sq[3]);
    __half hx = __float2half_rn(v.x), hy = __float2half_rn(v.y);
    __half hz = __float2half_rn(v.z), hw = __float2half_rn(v.w);
    __half lx = __float2half_rn(v.x - __half2float(hx));
    __half ly = __float2half_rn(v.y - __half2float(hy));
    __half lz = __float2half_rn(v.z - __half2float(hz));
    __half lw = __float2half_rn(v.w - __half2float(hw));
    hi0 = __half_as_ushort(hx) | ((uint32_t)__half_as_ushort(hy) << 16);
    hi1 = __half_as_ushort(hz) | ((uint32_t)__half_as_ushort(hw) << 16);
    lo0 = __half_as_ushort(lx) | ((uint32_t)__half_as_ushort(ly) << 16);
    lo1 = __half_as_ushort(lz) | ((uint32_t)__half_as_ushort(lw) << 16);
}

// ---------------------------------------------------------------------------
// Kernel A1: tar conversion, C split 8 ways (64 blocks). Partial sumsq out.
// ---------------------------------------------------------------------------
__global__ __launch_bounds__(256)
void conv_tar1(const float* __restrict__ tar)
{
    const int b  = blockIdx.x >> 3;
    const int cc = blockIdx.x & 7;
    const int t  = threadIdx.x;
    const int c0 = cc * 96;
    const float* p  = tar  + (size_t)b * Cdim * Tdim + (size_t)c0 * Tdim + t;
    __half* ph = g_AH + (size_t)b * Cdim * Tdim + (size_t)c0 * Tdim + t;
    __half* pl = g_AL + (size_t)b * Cdim * Tdim + (size_t)c0 * Tdim + t;

    float sq = 0.f;
#pragma unroll 8
    for (int c = 0; c < 96; c++) {
        float x = __ldg(p + (size_t)c * Tdim);
        sq = fmaf(x, x, sq);
        __half h = __float2half_rn(x);
        __half l = __float2half_rn(x - __half2float(h));
        ph[(size_t)c * Tdim] = h;
        pl[(size_t)c * Tdim] = l;
    }
    g_psq[cc][b * Tdim + t] = sq;
}

// ---------------------------------------------------------------------------
// Kernel A2: reduce partial sumsq (fixed order -> deterministic) + tar norms
// ---------------------------------------------------------------------------
__global__ __launch_bounds__(256)
void conv_tar2(const float* __restrict__ tarm)
{
    const int b = blockIdx.x;
    const int t = threadIdx.x;
    float s = 0.f;
#pragma unroll
    for (int i = 0; i < 8; i++) s += g_psq[i][b * Tdim + t];
    float inv = 1.0f / fmaxf(sqrtf(s), 1e-12f);
    g_fT[b * Tdim + t] = inv * tarm[b * Tdim + t];
}

// ---------------------------------------------------------------------------
// Kernel B: M=256 x N=64 GEMM, K-chunk=16, 4-stage A cp.async pipeline,
// distance-2 register prefetch for B (LDG -> cvt slack > 1 full iteration),
// deferred B cvt in MMA shadow. 1024 CTAs, 256 threads, 2 CTAs/SM.
// ---------------------------------------------------------------------------
#define ASTG      16384     // A stage: hi 8KB + lo 8KB
#define BBASE     65536     // 4 stages * 16KB
#define BBUF      4096      // B buf: hi 2KB + lo 2KB
#define DYN_SMEM  (BBASE + 2 * BBUF)   // 73728

__global__ __launch_bounds__(256, 2)
void sim_gemm(const float* __restrict__ src, const float* __restrict__ srcm)
{
    extern __shared__ char dsm[];
    __shared__ float fA[256], fB[64], fBsq[64];
    __shared__ unsigned long long rowp[256], colp[64];

    const uint32_t sb = smem_u32(dsm);
    const int tid  = threadIdx.x;
    const int w    = tid >> 5;
    const int lane = tid & 31;
    const int blk  = blockIdx.x;
    const int bn   = blk >> 2;
    const int sq4  = blk & 3;          // s-quarter
    const int s0   = sq4 << 6;
    const int b    = bn >> 5;

    fA[tid] = g_fT[b * Tdim + tid];
    rowp[tid] = 0ULL;
    if (tid < 64) { fBsq[tid] = 0.f; colp[tid] = 0ULL; }

    // A cp.async mapping: k = tid>>4, two 16B units u0, u0+1 per plane
    const int ka = tid >> 4;
    const int u0 = (tid & 15) * 2;
    const __half* gAh = g_AH + (size_t)b * Cdim * Tdim + (size_t)ka * Tdim;
    const __half* gAl = g_AL + (size_t)b * Cdim * Tdim + (size_t)ka * Tdim;
    const size_t gstep = (size_t)16 * Tdim;
    const uint32_t adst0 = (uint32_t)ka * 512 +
                           (uint32_t)(((u0 & 24) | ((u0 ^ ka) & 7)) << 4);
    const uint32_t adst1 = (uint32_t)ka * 512 +
                           (uint32_t)((((u0 + 1) & 24) | (((u0 + 1) ^ ka) & 7)) << 4);

    // B mapping: k = tid>>4, q = tid&15, float4 at s = q*4
    const int q = tid & 15;
    const float* gB = src + (size_t)bn * Cdim * Tdim + (size_t)ka * Tdim + s0 + q * 4;
    const uint32_t bsts = (uint32_t)ka * 128 +
                          (uint32_t)(((q >> 1) ^ (ka & 7)) << 4) + (q & 1) * 8;

    // warp tile 64x32
    const int wm = w & 3;
    const int wn = w >> 2;
    const int warp_m0 = wm * 64;
    const int warp_n0 = wn * 32;

    // ldmatrix offsets (A plane row = 512B, B plane row = 128B)
    const int krA = (lane & 7) + ((lane >> 4) << 3);
    const int mA8 = ((lane >> 3) & 1) << 3;
    uint32_t aoff[4];
#pragma unroll
    for (int mi = 0; mi < 4; mi++) {
        int mcol = warp_m0 + mi * 16 + mA8;
        aoff[mi] = (uint32_t)krA * 512 + (uint32_t)(((mcol >> 3) ^ (krA & 7)) << 4);
    }
    const int krB = (lane & 7) + (((lane >> 3) & 1) << 3);
    const int nB8 = ((lane >> 4) & 1) << 3;
    uint32_t boff[2];
#pragma unroll
    for (int t2 = 0; t2 < 2; t2++) {
        int ncol = warp_n0 + t2 * 16 + nB8;
        boff[t2] = (uint32_t)krB * 128 + (uint32_t)(((ncol >> 3) ^ (krB & 7)) << 4);
    }

    float acc[4][4][4];
#pragma unroll
    for (int i = 0; i < 4; i++)
#pragma unroll
        for (int j = 0; j < 4; j++)
#pragma unroll
            for (int e = 0; e < 4; e++) acc[i][j][e] = 0.f;

    float sqr[4] = {0.f, 0.f, 0.f, 0.f};

    // prologue: A chunks 0,1,2 -> stages 0,1,2; B chunk 0 -> cvt -> buf0;
    // B chunk 1 -> register slot rb[1] (distance-2 prefetch pipeline)
#pragma unroll
    for (int pc = 0; pc < 3; pc++) {
        const uint32_t ab = sb + (uint32_t)pc * ASTG;
        cpasync16(ab + adst0,        gAh + pc * gstep + u0 * 8);
        cpasync16(ab + adst1,        gAh + pc * gstep + (u0 + 1) * 8);
        cpasync16(ab + 8192 + adst0, gAl + pc * gstep + u0 * 8);
        cpasync16(ab + 8192 + adst1, gAl + pc * gstep + (u0 + 1) * 8);
        CP_COMMIT();
    }
    float4 rb0, rb1;          // rb[(chunk)&1] holds chunk's B data
    {
        float4 r0 = *(const float4*)gB;               // chunk 0
        uint32_t h0, h1, l0, l1;
        cvt4(r0, sqr, h0, h1, l0, l1);
        const uint32_t bw = sb + BBASE;
        sts64(bw + bsts,        h0, h1);
        sts64(bw + 2048 + bsts, l0, l1);
        rb1 = *(const float4*)(gB + gstep);           // chunk 1 -> rb[1]
    }
    CP_WAIT(2);
    __syncthreads();

    for (int c = 0; c < 48; c++) {
        const uint32_t bbr   = sb + BBASE + (uint32_t)(c & 1) * BBUF;
        const uint32_t abase = sb + (uint32_t)(c & 3) * ASTG;

        // A prefetch chunk c+3 (distance 3); always commit to keep counts
        if (c + 3 < 48) {
            const uint32_t nb = sb + (uint32_t)((c + 3) & 3) * ASTG;
            const size_t go = (size_t)(c + 3) * gstep;
            cpasync16(nb + adst0,        gAh + go + u0 * 8);
            cpasync16(nb + adst1,        gAh + go + (u0 + 1) * 8);
            cpasync16(nb + 8192 + adst0, gAl + go + u0 * 8);
            cpasync16(nb + 8192 + adst1, gAl + go + (u0 + 1) * 8);
        }
        CP_COMMIT();

        // B register prefetch chunk c+2 into rb[(c+2)&1] == rb[c&1]
        if (c + 2 < 48) {
            if ((c & 1) == 0) rb0 = *(const float4*)(gB + (size_t)(c + 2) * gstep);
            else              rb1 = *(const float4*)(gB + (size_t)(c + 2) * gstep);
        }

        // B fragments for this chunk (shared across all mi)
        uint32_t Bh[2][4], Bl[2][4];
#pragma unroll
        for (int t2 = 0; t2 < 2; t2++) {
            ldm4t(Bh[t2], bbr + boff[t2]);
            ldm4t(Bl[t2], bbr + 2048 + boff[t2]);
        }

        // ---- MMA half 1: mi = 0,1 (R12 grouping) ----
#pragma unroll
        for (int mi = 0; mi < 2; mi++) {
            uint32_t Ah[4], Al[4];
            ldm4t(Ah, abase + aoff[mi]);
            ldm4t(Al, abase + 8192 + aoff[mi]);
#pragma unroll
            for (int ni = 0; ni < 4; ni++) {
                const uint32_t* bh = &Bh[ni >> 1][(ni & 1) * 2];
                const uint32_t* bl = &Bl[ni >> 1][(ni & 1) * 2];
                mma16816(acc[mi][ni], Ah, bh);
                mma16816(acc[mi][ni], Ah, bl);
                mma16816(acc[mi][ni], Al, bh);
            }
        }

        // ---- deferred B convert for chunk c+1 (loaded a full iter ago) ----
        if (c < 47) {
            const uint32_t bw = sb + BBASE + (uint32_t)((c + 1) & 1) * BBUF;
            float4 rv = ((c + 1) & 1) ? rb1 : rb0;
            uint32_t h0, h1, l0, l1;
            cvt4(rv, sqr, h0, h1, l0, l1);
            sts64(bw + bsts,        h0, h1);
            sts64(bw + 2048 + bsts, l0, l1);
        }

        // ---- MMA half 2: mi = 2,3 ----
#pragma unroll
        for (int mi = 2; mi < 4; mi++) {
            uint32_t Ah[4], Al[4];
            ldm4t(Ah, abase + aoff[mi]);
            ldm4t(Al, abase + 8192 + aoff[mi]);
#pragma unroll
            for (int ni = 0; ni < 4; ni++) {
                const uint32_t* bh = &Bh[ni >> 1][(ni & 1) * 2];
                const uint32_t* bl = &Bl[ni >> 1][(ni & 1) * 2];
                mma16816(acc[mi][ni], Ah, bh);
                mma16816(acc[mi][ni], Ah, bl);
                mma16816(acc[mi][ni], Al, bh);
            }
        }

        CP_WAIT(2);
        __syncthreads();
    }

    // src norms (s-quarter complete in this CTA)
#pragma unroll
    for (int j = 0; j < 4; j++) atomicAdd(&fBsq[q * 4 + j], sqr[j]);
    __syncthreads();
    if (tid < 64) {
        float inv = 1.0f / fmaxf(sqrtf(fBsq[tid]), 1e-12f);
        fB[tid] = inv * srcm[bn * Tdim + s0 + tid];
    }
    __syncthreads();

    // epilogue: scale + threshold + packed dual max/argmax
    const int qrow = lane >> 2;
    const int qcol = (lane & 3) * 2;
    unsigned long long rmax[8], cmax[8];
#pragma unroll
    for (int i = 0; i < 8; i++) { rmax[i] = 0ULL; cmax[i] = 0ULL; }

#pragma unroll
    for (int mi = 0; mi < 4; mi++) {
        const int m0l = warp_m0 + mi * 16 + qrow;       // global t
        const float fa0 = fA[m0l], fa1 = fA[m0l + 8];
        const int tg0 = m0l, tg1 = m0l + 8;
#pragma unroll
        for (int ni = 0; ni < 4; ni++) {
            const int n0l = warp_n0 + ni * 8 + qcol;    // local s in [0,64)
            const float fb0 = fB[n0l], fb1 = fB[n0l + 1];
            const int sg0 = s0 + n0l, sg1 = sg0 + 1;    // global s
            const float* a = acc[mi][ni];
            float v00 = a[0] * fa0 * fb0; if (v00 < 0.05f) v00 = 0.f;
            float v01 = a[1] * fa0 * fb1; if (v01 < 0.05f) v01 = 0.f;
            float v10 = a[2] * fa1 * fb0; if (v10 < 0.05f) v10 = 0.f;
            float v11 = a[3] * fa1 * fb1; if (v11 < 0.05f) v11 = 0.f;
            rmax[mi * 2 + 0] = umaxll(rmax[mi * 2 + 0],
                                      umaxll(packsi(v00, sg0), packsi(v01, sg1)));
            rmax[mi * 2 + 1] = umaxll(rmax[mi * 2 + 1],
                                      umaxll(packsi(v10, sg0), packsi(v11, sg1)));
            cmax[ni * 2 + 0] = umaxll(cmax[ni * 2 + 0],
                                      umaxll(packsi(v00, tg0), packsi(v10, tg1)));
            cmax[ni * 2 + 1] = umaxll(cmax[ni * 2 + 1],
                                      umaxll(packsi(v01, tg0), packsi(v11, tg1)));
        }
    }
#pragma unroll
    for (int mi = 0; mi < 4; mi++) {
        atomicMax(&rowp[warp_m0 + mi * 16 + qrow],     rmax[mi * 2 + 0]);
        atomicMax(&rowp[warp_m0 + mi * 16 + qrow + 8], rmax[mi * 2 + 1]);
    }
#pragma unroll
    for (int ni = 0; ni < 4; ni++) {
        atomicMax(&colp[warp_n0 + ni * 8 + qcol],     cmax[ni * 2 + 0]);
        atomicMax(&colp[warp_n0 + ni * 8 + qcol + 1], cmax[ni * 2 + 1]);
    }
    __syncthreads();

    g_t2sP[sq4][bn * Tdim + tid] = rowp[tid];
    if (tid < 64) g_s2t[bn * Tdim + s0 + tid] = colp[tid];
}

// ---------------------------------------------------------------------------
// Kernel C: merge row quarters + cycle consistency + counts + sim_avg
// ---------------------------------------------------------------------------
__global__ void stage2(const float* __restrict__ srcm,
                       const float* __restrict__ tarm,
                       float* __restrict__ out)
{
    const int bn = blockIdx.x;
    const int b  = bn >> 5;
    const int t  = threadIdx.x;

    unsigned long long pt = umaxll(
        umaxll(g_t2sP[0][bn * Tdim + t], g_t2sP[1][bn * Tdim + t]),
        umaxll(g_t2sP[2][bn * Tdim + t], g_t2sP[3][bn * Tdim + t]));
    g_t2sP[0][bn * Tdim + t] = pt;
    float sc_t2s = __uint_as_float((unsigned)(pt >> 32));
    int   i_t2s  = (int)(~(unsigned)pt);

    int i_s2t_here = (int)(~(unsigned)g_s2t[bn * Tdim + t]);

    unsigned long long psi = g_s2t[bn * Tdim + i_t2s];
    float sc_s2t_i = __uint_as_float((unsigned)(psi >> 32));
    int   i_s2s    = (int)(~(unsigned)psi);

    int dx = (i_s2s & 15) - (t & 15);
    int dy = (i_s2s >> 4) - (t >> 4);
    bool cyc  = (dx * dx + dy * dy <= 4) && (sc_s2t_i >= 0.05f);
    bool msim = (sc_t2s >= 0.05f);

    float m = 0.f;
    if (msim && cyc && i_s2t_here != 0 && i_t2s != 0)
        m = tarm[b * Tdim + t] * srcm[bn * Tdim + i_t2s];

    g_mask_all[bn * Tdim + t] = m;

    __shared__ float s1[Tdim], s2[Tdim];
    s1[t] = m;
    s2[t] = sc_t2s * m;
    __syncthreads();
    for (int off = Tdim / 2; off > 0; off >>= 1) {
        if (t < off) { s1[t] += s1[t + off]; s2[t] += s2[t + off]; }
        __syncthreads();
    }
    if (t == 0) {
        float cnt = s1[0];
        out[OFF_CNT + bn] = cnt;
        g_simavg[bn] = (cnt > 0.f) ? (s2[0] * (1.0f / 256.0f)) : 0.f;
    }
}

// ---------------------------------------------------------------------------
// Kernel D: top-K selection (stable ties) + output formatting
// ---------------------------------------------------------------------------
__global__ void topk_format(float* __restrict__ out)
{
    __shared__ int sel[KTOP];
    const int b = blockIdx.x;
    if (threadIdx.x == 0) {
        float sa[Ndim]; bool used[Ndim];
#pragma unroll
        for (int n = 0; n < Ndim; n++) { sa[n] = g_simavg[b * Ndim + n]; used[n] = false; }
        for (int k = 0; k < KTOP; k++) {
            float best = -1.f; int bi = 0;
            for (int n = 0; n < Ndim; n++)
                if (!used[n] && sa[n] > best) { best = sa[n]; bi = n; }
            used[bi] = true;
            sel[k] = bi;
            out[OFF_ID    + b * KTOP + k] = (float)bi;
            out[OFF_SCORE + b * KTOP + k] = best;
        }
    }
    __syncthreads();
    const int t = threadIdx.x;
#pragma unroll
    for (int k = 0; k < KTOP; k++) {
        const int n   = sel[k];
        const int bk  = b * KTOP + k;
        const int bnT = (b * Ndim + n) * Tdim + t;

        unsigned long long pt = g_t2sP[0][bnT];
        float sc = __uint_as_float((unsigned)(pt >> 32));
        int  idx = (int)(~(unsigned)pt);
        float m  = g_mask_all[bnT];

        out[OFF_SPTS + bk * Tdim + t] = sc;
        const int o = (bk * Tdim + t) * 2;
        if (m != 0.f) {
            out[OFF_TAR + o]     = (float)(t & 15);
            out[OFF_TAR + o + 1] = (float)(t >> 4);
            out[OFF_SRC + o]     = (float)(idx & 15);
            out[OFF_SRC + o + 1] = (float)(idx >> 4);
        } else {
            out[OFF_TAR + o]     = -1.f;
            out[OFF_TAR + o + 1] = -1.f;
            out[OFF_SRC + o]     = -1.f;
            out[OFF_SRC + o + 1] = -1.f;
        }
    }
}

// ---------------------------------------------------------------------------
extern "C" void kernel_launch(void* const* d_in, const int* in_sizes, int n_in,
                              void* d_out, int out_size)
{
    const float* src  = (const float*)d_in[0];
    const float* tar  = (const float*)d_in[1];
    const float* srcm = (const float*)d_in[2];
    const float* tarm = (const float*)d_in[3];
    float* out = (float*)d_out;

    cudaFuncSetAttribute(sim_gemm, cudaFuncAttributeMaxDynamicSharedMemorySize,
                         DYN_SMEM);

    conv_tar1<<<Bdim * 8, 256>>>(tar);
    conv_tar2<<<Bdim, 256>>>(tarm);
    sim_gemm<<<BNprod * 4, 256, DYN_SMEM>>>(src, srcm);
    stage2<<<BNprod, Tdim>>>(srcm, tarm, out);
    topk_format<<<Bdim, 256>>>(out);
}

// round 16
// speedup vs baseline: 1.2149x; 1.2149x over previous
#include <cuda_runtime.h>
#include <cuda_fp16.h>
#include <cstdint>

#define Bdim   8
#define Ndim   32
#define Cdim   768
#define Tdim   256
#define KTOP   5
#define BNprod (Bdim * Ndim)

// Output layout (float32, concatenated in return-tuple order)
#define OFF_ID      0
#define OFF_SCORE   40
#define OFF_SPTS    80
#define OFF_TAR     10320
#define OFF_SRC     30800
#define OFF_CNT     51280

// ---------------- global scratch ----------------
__device__ unsigned long long g_t2sP[4][BNprod * Tdim];  // row max parts (s-quarters)
__device__ unsigned long long g_s2t[BNprod * Tdim];      // col max (complete per CTA)
__device__ float              g_mask_all[BNprod * Tdim];
__device__ float              g_simavg[BNprod];
__device__ int                g_cnt[Bdim];               // zero-init; reset by last block

__device__ __half g_AH[(size_t)Bdim * Cdim * Tdim];      // tar hi (3.1MB)
__device__ __half g_AL[(size_t)Bdim * Cdim * Tdim];      // tar lo
__device__ float  g_fT[Bdim * Tdim];                     // inv_norm * tar_mask
__device__ float  g_psq[8][Bdim * Tdim];                 // partial sumsq (C-chunks)

static __device__ __forceinline__ unsigned long long packsi(float score, int idx) {
    return ((unsigned long long)__float_as_uint(score) << 32) |
           (unsigned long long)(unsigned)(~idx);
}
static __device__ __forceinline__ unsigned long long umaxll(unsigned long long a,
                                                            unsigned long long b) {
    return a > b ? a : b;
}
static __device__ __forceinline__ uint32_t smem_u32(const void* p) {
    uint32_t a;
    asm("{ .reg .u64 t; cvta.to.shared.u64 t, %1; cvt.u32.u64 %0, t; }" : "=r"(a) : "l"(p));
    return a;
}
static __device__ __forceinline__ void ldm4t(uint32_t* r, uint32_t addr) {
    asm volatile("ldmatrix.sync.aligned.m8n8.x4.trans.shared.b16 {%0,%1,%2,%3}, [%4];"
                 : "=r"(r[0]), "=r"(r[1]), "=r"(r[2]), "=r"(r[3]) : "r"(addr));
}
static __device__ __forceinline__ void mma16816(float* d, const uint32_t* a,
                                                const uint32_t* b) {
    asm volatile(
        "mma.sync.aligned.m16n8k16.row.col.f32.f16.f16.f32 "
        "{%0,%1,%2,%3}, {%4,%5,%6,%7}, {%8,%9}, {%0,%1,%2,%3};"
        : "+f"(d[0]), "+f"(d[1]), "+f"(d[2]), "+f"(d[3])
        : "r"(a[0]), "r"(a[1]), "r"(a[2]), "r"(a[3]), "r"(b[0]), "r"(b[1]));
}
static __device__ __forceinline__ void cpasync16(uint32_t dst, const void* src) {
    asm volatile("cp.async.cg.shared.global [%0], [%1], 16;" :: "r"(dst), "l"(src)
                 : "memory");
}
#define CP_COMMIT()  asm volatile("cp.async.commit_group;" ::: "memory")
#define CP_WAIT(n)   asm volatile("cp.async.wait_group %0;" :: "n"(n) : "memory")

static __device__ __forceinline__ void sts64(uint32_t addr, uint32_t r0, uint32_t r1) {
    asm volatile("st.shared.v2.b32 [%0], {%1, %2};" :: "r"(addr), "r"(r0), "r"(r1)
                 : "memory");
}
static __device__ __forceinline__ void cvt4(float4 v, float* sq,
                                            uint32_t& hi0, uint32_t& hi1,
                                            uint32_t& lo0, uint32_t& lo1) {
    sq[0] = fmaf(v.x, v.x, sq[0]);
    sq[1] = fmaf(v.y, v.y, sq[1]);
    sq[2] = fmaf(v.z, v.z, sq[2]);
    sq[3] = fmaf(v.w, v.w, sq[3]);
    __half hx = __float2half_rn(v.x), hy = __float2half_rn(v.y);
    __half hz = __float2half_rn(v.z), hw = __float2half_rn(v.w);
    __half lx = __float2half_rn(v.x - __half2float(hx));
    __half ly = __float2half_rn(v.y - __half2float(hy));
    __half lz = __float2half_rn(v.z - __half2float(hz));
    __half lw = __float2half_rn(v.w - __half2float(hw));
    hi0 = __half_as_ushort(hx) | ((uint32_t)__half_as_ushort(hy) << 16);
    hi1 = __half_as_ushort(hz) | ((uint32_t)__half_as_ushort(hw) << 16);
    lo0 = __half_as_ushort(lx) | ((uint32_t)__half_as_ushort(ly) << 16);
    lo1 = __half_as_ushort(lz) | ((uint32_t)__half_as_ushort(lw) << 16);
}

// ---------------------------------------------------------------------------
// Kernel A1: tar conversion, C split 8 ways (64 blocks). Partial sumsq out.
// ---------------------------------------------------------------------------
__global__ __launch_bounds__(256)
void conv_tar1(const float* __restrict__ tar)
{
    const int b  = blockIdx.x >> 3;
    const int cc = blockIdx.x & 7;
    const int t  = threadIdx.x;
    const int c0 = cc * 96;
    const float* p  = tar  + (size_t)b * Cdim * Tdim + (size_t)c0 * Tdim + t;
    __half* ph = g_AH + (size_t)b * Cdim * Tdim + (size_t)c0 * Tdim + t;
    __half* pl = g_AL + (size_t)b * Cdim * Tdim + (size_t)c0 * Tdim + t;

    float sq = 0.f;
#pragma unroll 8
    for (int c = 0; c < 96; c++) {
        float x = __ldg(p + (size_t)c * Tdim);
        sq = fmaf(x, x, sq);
        __half h = __float2half_rn(x);
        __half l = __float2half_rn(x - __half2float(h));
        ph[(size_t)c * Tdim] = h;
        pl[(size_t)c * Tdim] = l;
    }
    g_psq[cc][b * Tdim + t] = sq;
}

// ---------------------------------------------------------------------------
// Kernel A2: reduce partial sumsq (fixed order -> deterministic) + tar norms
// ---------------------------------------------------------------------------
__global__ __launch_bounds__(256)
void conv_tar2(const float* __restrict__ tarm)
{
    const int b = blockIdx.x;
    const int t = threadIdx.x;
    float s = 0.f;
#pragma unroll
    for (int i = 0; i < 8; i++) s += g_psq[i][b * Tdim + t];
    float inv = 1.0f / fmaxf(sqrtf(s), 1e-12f);
    g_fT[b * Tdim + t] = inv * tarm[b * Tdim + t];
}

// ---------------------------------------------------------------------------
// Kernel B: M=256 x N=64 GEMM, K-chunk=16, 4-stage A cp.async pipeline,
// B cvt deferred into MMA shadow (R12 verbatim). 1024 CTAs, 2 CTAs/SM.
// ---------------------------------------------------------------------------
#define ASTG      16384     // A stage: hi 8KB + lo 8KB
#define BBASE     65536     // 4 stages * 16KB
#define BBUF      4096      // B buf: hi 2KB + lo 2KB
#define DYN_SMEM  (BBASE + 2 * BBUF)   // 73728

__global__ __launch_bounds__(256, 2)
void sim_gemm(const float* __restrict__ src, const float* __restrict__ srcm)
{
    extern __shared__ char dsm[];
    __shared__ float fA[256], fB[64], fBsq[64];
    __shared__ unsigned long long rowp[256], colp[64];

    const uint32_t sb = smem_u32(dsm);
    const int tid  = threadIdx.x;
    const int w    = tid >> 5;
    const int lane = tid & 31;
    const int blk  = blockIdx.x;
    const int bn   = blk >> 2;
    const int sq4  = blk & 3;          // s-quarter
    const int s0   = sq4 << 6;
    const int b    = bn >> 5;

    fA[tid] = g_fT[b * Tdim + tid];
    rowp[tid] = 0ULL;
    if (tid < 64) { fBsq[tid] = 0.f; colp[tid] = 0ULL; }

    // A cp.async mapping: k = tid>>4, two 16B units u0, u0+1 per plane
    const int ka = tid >> 4;
    const int u0 = (tid & 15) * 2;
    const __half* gAh = g_AH + (size_t)b * Cdim * Tdim + (size_t)ka * Tdim;
    const __half* gAl = g_AL + (size_t)b * Cdim * Tdim + (size_t)ka * Tdim;
    const size_t gstep = (size_t)16 * Tdim;
    const uint32_t adst0 = (uint32_t)ka * 512 +
                           (uint32_t)(((u0 & 24) | ((u0 ^ ka) & 7)) << 4);
    const uint32_t adst1 = (uint32_t)ka * 512 +
                           (uint32_t)((((u0 + 1) & 24) | (((u0 + 1) ^ ka) & 7)) << 4);

    // B mapping: k = tid>>4, q = tid&15, float4 at s = q*4
    const int q = tid & 15;
    const float* gB = src + (size_t)bn * Cdim * Tdim + (size_t)ka * Tdim + s0 + q * 4;
    const uint32_t bsts = (uint32_t)ka * 128 +
                          (uint32_t)(((q >> 1) ^ (ka & 7)) << 4) + (q & 1) * 8;

    // warp tile 64x32
    const int wm = w & 3;
    const int wn = w >> 2;
    const int warp_m0 = wm * 64;
    const int warp_n0 = wn * 32;

    // ldmatrix offsets (A plane row = 512B, B plane row = 128B)
    const int krA = (lane & 7) + ((lane >> 4) << 3);
    const int mA8 = ((lane >> 3) & 1) << 3;
    uint32_t aoff[4];
#pragma unroll
    for (int mi = 0; mi < 4; mi++) {
        int mcol = warp_m0 + mi * 16 + mA8;
        aoff[mi] = (uint32_t)krA * 512 + (uint32_t)(((mcol >> 3) ^ (krA & 7)) << 4);
    }
    const int krB = (lane & 7) + (((lane >> 3) & 1) << 3);
    const int nB8 = ((lane >> 4) & 1) << 3;
    uint32_t boff[2];
#pragma unroll
    for (int t2 = 0; t2 < 2; t2++) {
        int ncol = warp_n0 + t2 * 16 + nB8;
        boff[t2] = (uint32_t)krB * 128 + (uint32_t)(((ncol >> 3) ^ (krB & 7)) << 4);
    }

    float acc[4][4][4];
#pragma unroll
    for (int i = 0; i < 4; i++)
#pragma unroll
        for (int j = 0; j < 4; j++)
#pragma unroll
            for (int e = 0; e < 4; e++) acc[i][j][e] = 0.f;

    float sqr[4] = {0.f, 0.f, 0.f, 0.f};

    // prologue: A chunks 0,1,2 -> stages 0,1,2 (3 groups); B chunk 0 -> buf0
#pragma unroll
    for (int pc = 0; pc < 3; pc++) {
        const uint32_t ab = sb + (uint32_t)pc * ASTG;
        cpasync16(ab + adst0,        gAh + pc * gstep + u0 * 8);
        cpasync16(ab + adst1,        gAh + pc * gstep + (u0 + 1) * 8);
        cpasync16(ab + 8192 + adst0, gAl + pc * gstep + u0 * 8);
        cpasync16(ab + 8192 + adst1, gAl + pc * gstep + (u0 + 1) * 8);
        CP_COMMIT();
    }
    {
        float4 r0 = *(const float4*)gB;
        uint32_t h0, h1, l0, l1;
        cvt4(r0, sqr, h0, h1, l0, l1);
        const uint32_t bw = sb + BBASE;
        sts64(bw + bsts,        h0, h1);
        sts64(bw + 2048 + bsts, l0, l1);
    }
    CP_WAIT(2);
    __syncthreads();

    for (int c = 0; c < 48; c++) {
        const uint32_t bbr   = sb + BBASE + (uint32_t)(c & 1) * BBUF;
        const uint32_t abase = sb + (uint32_t)(c & 3) * ASTG;

        // A prefetch chunk c+3 (distance 3); always commit to keep counts
        if (c + 3 < 48) {
            const uint32_t nb = sb + (uint32_t)((c + 3) & 3) * ASTG;
            const size_t go = (size_t)(c + 3) * gstep;
            cpasync16(nb + adst0,        gAh + go + u0 * 8);
            cpasync16(nb + adst1,        gAh + go + (u0 + 1) * 8);
            cpasync16(nb + 8192 + adst0, gAl + go + u0 * 8);
            cpasync16(nb + 8192 + adst1, gAl + go + (u0 + 1) * 8);
        }
        CP_COMMIT();

        float4 rbn;
        if (c < 47) rbn = *(const float4*)(gB + (size_t)(c + 1) * gstep);

        // B fragments for this chunk (shared across all mi)
        uint32_t Bh[2][4], Bl[2][4];
#pragma unroll
        for (int t2 = 0; t2 < 2; t2++) {
            ldm4t(Bh[t2], bbr + boff[t2]);
            ldm4t(Bl[t2], bbr + 2048 + boff[t2]);
        }

        // ---- MMA half 1: mi = 0,1 ----
#pragma unroll
        for (int mi = 0; mi < 2; mi++) {
            uint32_t Ah[4], Al[4];
            ldm4t(Ah, abase + aoff[mi]);
            ldm4t(Al, abase + 8192 + aoff[mi]);
#pragma unroll
            for (int ni = 0; ni < 4; ni++) {
                const uint32_t* bh = &Bh[ni >> 1][(ni & 1) * 2];
                const uint32_t* bl = &Bl[ni >> 1][(ni & 1) * 2];
                mma16816(acc[mi][ni], Ah, bh);
                mma16816(acc[mi][ni], Ah, bl);
                mma16816(acc[mi][ni], Al, bh);
            }
        }

        // ---- deferred B convert for chunk c+1 into the OTHER buffer ----
        if (c < 47) {
            const uint32_t bw = sb + BBASE + (uint32_t)((c + 1) & 1) * BBUF;
            uint32_t h0, h1, l0, l1;
            cvt4(rbn, sqr, h0, h1, l0, l1);
            sts64(bw + bsts,        h0, h1);
            sts64(bw + 2048 + bsts, l0, l1);
        }

        // ---- MMA half 2: mi = 2,3 ----
#pragma unroll
        for (int mi = 2; mi < 4; mi++) {
            uint32_t Ah[4], Al[4];
            ldm4t(Ah, abase + aoff[mi]);
            ldm4t(Al, abase + 8192 + aoff[mi]);
#pragma unroll
            for (int ni = 0; ni < 4; ni++) {
                const uint32_t* bh = &Bh[ni >> 1][(ni & 1) * 2];
                const uint32_t* bl = &Bl[ni >> 1][(ni & 1) * 2];
                mma16816(acc[mi][ni], Ah, bh);
                mma16816(acc[mi][ni], Ah, bl);
                mma16816(acc[mi][ni], Al, bh);
            }
        }

        CP_WAIT(2);
        __syncthreads();
    }

    // src norms (s-quarter complete in this CTA)
#pragma unroll
    for (int j = 0; j < 4; j++) atomicAdd(&fBsq[q * 4 + j], sqr[j]);
    __syncthreads();
    if (tid < 64) {
        float inv = 1.0f / fmaxf(sqrtf(fBsq[tid]), 1e-12f);
        fB[tid] = inv * srcm[bn * Tdim + s0 + tid];
    }
    __syncthreads();

    // epilogue: scale + threshold + packed dual max/argmax
    const int qrow = lane >> 2;
    const int qcol = (lane & 3) * 2;
    unsigned long long rmax[8], cmax[8];
#pragma unroll
    for (int i = 0; i < 8; i++) { rmax[i] = 0ULL; cmax[i] = 0ULL; }

#pragma unroll
    for (int mi = 0; mi < 4; mi++) {
        const int m0l = warp_m0 + mi * 16 + qrow;       // global t
        const float fa0 = fA[m0l], fa1 = fA[m0l + 8];
        const int tg0 = m0l, tg1 = m0l + 8;
#pragma unroll
        for (int ni = 0; ni < 4; ni++) {
            const int n0l = warp_n0 + ni * 8 + qcol;    // local s in [0,64)
            const float fb0 = fB[n0l], fb1 = fB[n0l + 1];
            const int sg0 = s0 + n0l, sg1 = sg0 + 1;    // global s
            const float* a = acc[mi][ni];
            float v00 = a[0] * fa0 * fb0; if (v00 < 0.05f) v00 = 0.f;
            float v01 = a[1] * fa0 * fb1; if (v01 < 0.05f) v01 = 0.f;
            float v10 = a[2] * fa1 * fb0; if (v10 < 0.05f) v10 = 0.f;
            float v11 = a[3] * fa1 * fb1; if (v11 < 0.05f) v11 = 0.f;
            rmax[mi * 2 + 0] = umaxll(rmax[mi * 2 + 0],
                                      umaxll(packsi(v00, sg0), packsi(v01, sg1)));
            rmax[mi * 2 + 1] = umaxll(rmax[mi * 2 + 1],
                                      umaxll(packsi(v10, sg0), packsi(v11, sg1)));
            cmax[ni * 2 + 0] = umaxll(cmax[ni * 2 + 0],
                                      umaxll(packsi(v00, tg0), packsi(v10, tg1)));
            cmax[ni * 2 + 1] = umaxll(cmax[ni * 2 + 1],
                                      umaxll(packsi(v01, tg0), packsi(v11, tg1)));
        }
    }
#pragma unroll
    for (int mi = 0; mi < 4; mi++) {
        atomicMax(&rowp[warp_m0 + mi * 16 + qrow],     rmax[mi * 2 + 0]);
        atomicMax(&rowp[warp_m0 + mi * 16 + qrow + 8], rmax[mi * 2 + 1]);
    }
#pragma unroll
    for (int ni = 0; ni < 4; ni++) {
        atomicMax(&colp[warp_n0 + ni * 8 + qcol],     cmax[ni * 2 + 0]);
        atomicMax(&colp[warp_n0 + ni * 8 + qcol + 1], cmax[ni * 2 + 1]);
    }
    __syncthreads();

    g_t2sP[sq4][bn * Tdim + tid] = rowp[tid];
    if (tid < 64) g_s2t[bn * Tdim + s0 + tid] = colp[tid];
}

// ---------------------------------------------------------------------------
// Kernel C: merge row quarters + cycle consistency + counts + sim_avg,
// then the LAST block per batch b performs top-K + output formatting inline.
// ---------------------------------------------------------------------------
__global__ void stage2_fused(const float* __restrict__ srcm,
                             const float* __restrict__ tarm,
                             float* __restrict__ out)
{
    __shared__ int sel[KTOP];
    __shared__ int islast;
    const int bn = blockIdx.x;
    const int b  = bn >> 5;
    const int t  = threadIdx.x;

    unsigned long long pt = umaxll(
        umaxll(g_t2sP[0][bn * Tdim + t], g_t2sP[1][bn * Tdim + t]),
        umaxll(g_t2sP[2][bn * Tdim + t], g_t2sP[3][bn * Tdim + t]));
    g_t2sP[0][bn * Tdim + t] = pt;
    float sc_t2s = __uint_as_float((unsigned)(pt >> 32));
    int   i_t2s  = (int)(~(unsigned)pt);

    int i_s2t_here = (int)(~(unsigned)g_s2t[bn * Tdim + t]);

    unsigned long long psi = g_s2t[bn * Tdim + i_t2s];
    float sc_s2t_i = __uint_as_float((unsigned)(psi >> 32));
    int   i_s2s    = (int)(~(unsigned)psi);

    int dx = (i_s2s & 15) - (t & 15);
    int dy = (i_s2s >> 4) - (t >> 4);
    bool cyc  = (dx * dx + dy * dy <= 4) && (sc_s2t_i >= 0.05f);
    bool msim = (sc_t2s >= 0.05f);

    float m = 0.f;
    if (msim && cyc && i_s2t_here != 0 && i_t2s != 0)
        m = tarm[b * Tdim + t] * srcm[bn * Tdim + i_t2s];

    g_mask_all[bn * Tdim + t] = m;

    __shared__ float s1[Tdim], s2[Tdim];
    s1[t] = m;
    s2[t] = sc_t2s * m;
    __syncthreads();
    for (int off = Tdim / 2; off > 0; off >>= 1) {
        if (t < off) { s1[t] += s1[t + off]; s2[t] += s2[t + off]; }
        __syncthreads();
    }
    if (t == 0) {
        float cnt = s1[0];
        out[OFF_CNT + bn] = cnt;
        g_simavg[bn] = (cnt > 0.f) ? (s2[0] * (1.0f / 256.0f)) : 0.f;
    }

    // ---- last-block-per-batch: top-K selection + formatting ----
    __threadfence();
    if (t == 0) {
        int old = atomicAdd(&g_cnt[b], 1);
        islast = (old == Ndim - 1);
    }
    __syncthreads();
    if (!islast) return;

    if (t == 0) {
        g_cnt[b] = 0;                       // reset for next graph replay
        float sa[Ndim]; bool used[Ndim];
#pragma unroll
        for (int n = 0; n < Ndim; n++) { sa[n] = g_simavg[b * Ndim + n]; used[n] = false; }
        for (int k = 0; k < KTOP; k++) {
            float best = -1.f; int bi = 0;
            for (int n = 0; n < Ndim; n++)
                if (!used[n] && sa[n] > best) { best = sa[n]; bi = n; }
            used[bi] = true;
            sel[k] = bi;
            out[OFF_ID    + b * KTOP + k] = (float)bi;
            out[OFF_SCORE + b * KTOP + k] = best;
        }
    }
    __syncthreads();

#pragma unroll
    for (int k = 0; k < KTOP; k++) {
        const int n   = sel[k];
        const int bk  = b * KTOP + k;
        const int bnT = (b * Ndim + n) * Tdim + t;

        unsigned long long pk = g_t2sP[0][bnT];
        float sc = __uint_as_float((unsigned)(pk >> 32));
        int  idx = (int)(~(unsigned)pk);
        float mk = g_mask_all[bnT];

        out[OFF_SPTS + bk * Tdim + t] = sc;
        const int o = (bk * Tdim + t) * 2;
        if (mk != 0.f) {
            out[OFF_TAR + o]     = (float)(t & 15);
            out[OFF_TAR + o + 1] = (float)(t >> 4);
            out[OFF_SRC + o]     = (float)(idx & 15);
            out[OFF_SRC + o + 1] = (float)(idx >> 4);
        } else {
            out[OFF_TAR + o]     = -1.f;
            out[OFF_TAR + o + 1] = -1.f;
            out[OFF_SRC + o]     = -1.f;
            out[OFF_SRC + o + 1] = -1.f;
        }
    }
}

// ---------------------------------------------------------------------------
extern "C" void kernel_launch(void* const* d_in, const int* in_sizes, int n_in,
                              void* d_out, int out_size)
{
    const float* src  = (const float*)d_in[0];
    const float* tar  = (const float*)d_in[1];
    const float* srcm = (const float*)d_in[2];
    const float* tarm = (const float*)d_in[3];
    float* out = (float*)d_out;

    cudaFuncSetAttribute(sim_gemm, cudaFuncAttributeMaxDynamicSharedMemorySize,
                         DYN_SMEM);

    conv_tar1<<<Bdim * 8, 256>>>(tar);
    conv_tar2<<<Bdim, 256>>>(tarm);
    sim_gemm<<<BNprod * 4, 256, DYN_SMEM>>>(src, srcm);
    stage2_fused<<<BNprod, Tdim>>>(srcm, tarm, out);
}